// round 10
// baseline (speedup 1.0000x reference)
#include <cuda_runtime.h>
#include <math_constants.h>

// Until: out[b,t,x] = min(phi[b,t,x], max(psi[b,t,x], out[b,t-1,x])), out[-1] = -1e6.
// Single-pass chained scan (decoupled lookback). Monoid f(v)=min(A,max(B,v)):
//   compose (later∘earlier): A' = min(A2, max(B2, A1)), B' = max(B1, B2).
// R10: R9 structure, but 128-thread blocks / 10 CTAs per SM so co-resident
// blocks decorrelate their barrier+lookback windows and keep the LSU fed.

#define B_   64
#define T_   8192
#define X_   32
#define TC_  256                // time steps per chunk
#define C_   (T_ / TC_)         // 32 chunks per batch
#define NB_  (B_ * C_)          // 2048 blocks
#define NT_  128                // threads per block
#define SL_  16                 // t-slices per block (8 threads each)
#define PT_  (TC_ / SL_)        // 16 steps per thread
#define NW_  4                  // warps per block
#define SPW_ (SL_ / NW_)        // 4 slices per warp
#define LARGE_ 1.0e6f

__device__ float g_A[NB_ * X_];   // chunk aggregate A
__device__ float g_Bv[NB_ * X_];  // chunk aggregate B
__device__ float g_P[NB_ * X_];   // chunk inclusive prefix value
__device__ int   g_flag[NB_];     // epoch-tagged: 2e+1 aggregate, 2e+2 prefix
__device__ int   g_ticket;        // never reset; epoch = ticket / NB_

__global__ void __launch_bounds__(NT_, 10) until_scan(const float* __restrict__ phi,
                                                      const float* __restrict__ psi,
                                                      float* __restrict__ out) {
    __shared__ float sA[SL_][X_];     // per-slice aggregate A
    __shared__ float sB[SL_][X_];     // per-slice aggregate B
    __shared__ float sWA[NW_][X_];    // per-warp fold of its 4 slices
    __shared__ float sWB[NW_][X_];
    __shared__ float sGC[NW_][X_];    // carry entering each warp's slice group
    __shared__ int s_tic;

    const int tid = threadIdx.x;
    if (tid == 0) s_tic = atomicAdd(&g_ticket, 1);
    __syncthreads();
    const int traw = s_tic;
    const int e    = traw >> 11;          // epoch (NB_ = 2048)
    const int v    = traw & (NB_ - 1);
    const int b    = v % B_;              // breadth-first over chunks
    const int c    = v / B_;
    const int bc   = b * C_ + c;
    const int FLAG_AGG = 2 * e + 1;
    const int FLAG_PRE = 2 * e + 2;

    const int xg   = tid & 7;             // float4 group along x
    const int xq   = xg * 4;
    const int s    = tid >> 3;            // slice 0..15
    const int w    = tid >> 5;            // warp 0..3 (owns slices 4w..4w+3)
    const int lane = tid & 31;

    const size_t base = (size_t)b * T_ * X_ + (size_t)(c * TC_ + s * PT_) * X_ + xq;
    const float4* pp = (const float4*)(phi + base);
    const float4* qq = (const float4*)(psi + base);

    // ---------- phase 1: streaming slice aggregate (lines land in L2) ----------
    float4 A  = make_float4( CUDART_INF_F,  CUDART_INF_F,  CUDART_INF_F,  CUDART_INF_F);
    float4 Bc = make_float4(-CUDART_INF_F, -CUDART_INF_F, -CUDART_INF_F, -CUDART_INF_F);
#pragma unroll
    for (int i = 0; i < PT_; i++) {
        float4 p = pp[i * (X_ / 4)];
        float4 q = qq[i * (X_ / 4)];
        A.x = fminf(p.x, fmaxf(q.x, A.x));  Bc.x = fmaxf(q.x, Bc.x);
        A.y = fminf(p.y, fmaxf(q.y, A.y));  Bc.y = fmaxf(q.y, Bc.y);
        A.z = fminf(p.z, fmaxf(q.z, A.z));  Bc.z = fmaxf(q.z, Bc.z);
        A.w = fminf(p.w, fmaxf(q.w, A.w));  Bc.w = fmaxf(q.w, Bc.w);
    }
    sA[s][xq + 0] = A.x;  sA[s][xq + 1] = A.y;  sA[s][xq + 2] = A.z;  sA[s][xq + 3] = A.w;
    sB[s][xq + 0] = Bc.x; sB[s][xq + 1] = Bc.y; sB[s][xq + 2] = Bc.z; sB[s][xq + 3] = Bc.w;
    __syncwarp();   // slices 4w..4w+3 are written by warp w's own threads

    // ---------- fold level 1: warp w folds its 4 slices (lane = x) ----------
    {
        float wA =  CUDART_INF_F;
        float wB = -CUDART_INF_F;
#pragma unroll
        for (int j = 0; j < SPW_; j++) {
            const int sl = w * SPW_ + j;
            wA = fminf(sA[sl][lane], fmaxf(sB[sl][lane], wA));
            wB = fmaxf(sB[sl][lane], wB);
        }
        sWA[w][lane] = wA;
        sWB[w][lane] = wB;
    }
    __syncthreads();

    // ---------- warp 0: fold level 2, publish AGG, lookback, PRE, carries ----------
    if (tid < 32) {
        const int x = tid;
        float Ab =  CUDART_INF_F;
        float Bb = -CUDART_INF_F;
#pragma unroll
        for (int j = 0; j < NW_; j++) {
            Ab = fminf(sWA[j][x], fmaxf(sWB[j][x], Ab));
            Bb = fmaxf(sWB[j][x], Bb);
        }

        // Publish aggregate ONLY for c>0: chunk 0 goes straight to prefix,
        // so lookback never crosses a batch boundary.
        if (c > 0) {
            g_A[bc * X_ + x]  = Ab;
            g_Bv[bc * X_ + x] = Bb;
            __threadfence();
            __syncwarp();
            if (x == 0) *(volatile int*)&g_flag[bc] = FLAG_AGG;
        }

        float vin;
        if (c == 0) {
            vin = -LARGE_;
        } else {
            float accA =  CUDART_INF_F;
            float accB = -CUDART_INF_F;
            int j = bc - 1;
            while (true) {
                int f;
                do { f = *(volatile int*)&g_flag[j]; } while (f < FLAG_AGG);
                __threadfence();
                if (f == FLAG_PRE) {
                    vin = fminf(accA, fmaxf(accB, g_P[j * X_ + x]));
                    break;
                }
                float Aj = g_A[j * X_ + x];
                float Bj = g_Bv[j * X_ + x];
                accA = fminf(accA, fmaxf(accB, Aj));
                accB = fmaxf(accB, Bj);
                j--;
            }
        }

        // publish inclusive prefix FIRST (shortest tier-to-tier latency)
        float pre = fminf(Ab, fmaxf(Bb, vin));
        g_P[bc * X_ + x] = pre;
        __threadfence();
        __syncwarp();
        if (x == 0) *(volatile int*)&g_flag[bc] = FLAG_PRE;

        // carries entering each warp's slice group
        float g = vin;
#pragma unroll
        for (int j = 0; j < NW_; j++) {
            sGC[j][x] = g;
            g = fminf(sWA[j][x], fmaxf(sWB[j][x], g));
        }
    }
    __syncthreads();

    // ---------- per-thread slice carry (walk <=3 slices from warp-group carry) ----------
    float v0 = sGC[w][xq + 0];
    float v1 = sGC[w][xq + 1];
    float v2 = sGC[w][xq + 2];
    float v3 = sGC[w][xq + 3];
    for (int j = w * SPW_; j < s; j++) {
        v0 = fminf(sA[j][xq + 0], fmaxf(sB[j][xq + 0], v0));
        v1 = fminf(sA[j][xq + 1], fmaxf(sB[j][xq + 1], v1));
        v2 = fminf(sA[j][xq + 2], fmaxf(sB[j][xq + 2], v2));
        v3 = fminf(sA[j][xq + 3], fmaxf(sB[j][xq + 3], v3));
    }
    float4 vc = make_float4(v0, v1, v2, v3);

    // ---------- phase 2: reload (L2 hits), apply carry, stream out ----------
    float4* oo = (float4*)(out + base);
#pragma unroll
    for (int i = 0; i < PT_; i++) {
        float4 p = __ldcs(&pp[i * (X_ / 4)]);
        float4 q = __ldcs(&qq[i * (X_ / 4)]);
        vc.x = fminf(p.x, fmaxf(q.x, vc.x));
        vc.y = fminf(p.y, fmaxf(q.y, vc.y));
        vc.z = fminf(p.z, fmaxf(q.z, vc.z));
        vc.w = fminf(p.w, fmaxf(q.w, vc.w));
        __stcs(&oo[i * (X_ / 4)], vc);
    }
}

extern "C" void kernel_launch(void* const* d_in, const int* in_sizes, int n_in,
                              void* d_out, int out_size) {
    const float* phi = (const float*)d_in[0];
    const float* psi = (const float*)d_in[1];
    float* out = (float*)d_out;

    until_scan<<<NB_, NT_>>>(phi, psi, out);
}

// round 11
// speedup vs baseline: 1.1845x; 1.1845x over previous
#include <cuda_runtime.h>
#include <math_constants.h>

// Until: out[b,t,x] = min(phi[b,t,x], max(psi[b,t,x], out[b,t-1,x])), out[-1] = -1e6.
// Single-pass chained scan (decoupled lookback). Monoid f(v)=min(A,max(B,v)):
//   compose (later∘earlier): A' = min(A2, max(B2, A1)), B' = max(B1, B2).
// R11: R9 base + PARALLEL-WINDOW lookback: 8 warps poll 8 predecessors per
// round, warp 0 combines nearest-first. Walk latency /8.

#define B_   64
#define T_   8192
#define X_   32
#define TC_  256                // time steps per chunk
#define C_   (T_ / TC_)         // 32 chunks per batch
#define NB_  (B_ * C_)          // 2048 blocks
#define SL_  32                 // t-slices per block
#define PT_  (TC_ / SL_)        // 8 steps per thread
#define NW_  8                  // warps per block == lookback window size
#define SPW_ (SL_ / NW_)        // 4 slices per warp
#define LARGE_ 1.0e6f

__device__ float g_A[NB_ * X_];   // chunk aggregate A
__device__ float g_Bv[NB_ * X_];  // chunk aggregate B
__device__ float g_P[NB_ * X_];   // chunk inclusive prefix value
__device__ int   g_flag[NB_];     // epoch-tagged: 2e+1 aggregate, 2e+2 prefix
__device__ int   g_ticket;        // never reset; epoch = ticket / NB_

__global__ void __launch_bounds__(256, 6) until_scan(const float* __restrict__ phi,
                                                     const float* __restrict__ psi,
                                                     float* __restrict__ out) {
    __shared__ float sA[SL_][X_];     // per-slice aggregate A
    __shared__ float sB[SL_][X_];     // per-slice aggregate B
    __shared__ float sWA[NW_][X_];    // per-warp fold of its 4 slices
    __shared__ float sWB[NW_][X_];
    __shared__ float sGC[NW_][X_];    // carry entering each warp's slice group
    __shared__ float wLA[NW_][X_];    // lookback window payload (A or P)
    __shared__ float wLB[NW_][X_];    // lookback window payload (B)
    __shared__ int   wStat[NW_];      // 1 = PRE, 0 = AGG
    __shared__ float sFA[X_];         // block aggregate A
    __shared__ float sFB[X_];         // block aggregate B
    __shared__ int   s_done;
    __shared__ int   s_tic;

    const int tid = threadIdx.x;
    if (tid == 0) s_tic = atomicAdd(&g_ticket, 1);
    __syncthreads();
    const int traw = s_tic;
    const int e    = traw >> 11;          // epoch (NB_ = 2048)
    const int v    = traw & (NB_ - 1);
    const int b    = v % B_;              // breadth-first over chunks
    const int c    = v / B_;
    const int bc   = b * C_ + c;
    const int FLAG_AGG = 2 * e + 1;
    const int FLAG_PRE = 2 * e + 2;

    const int xg   = tid & 7;             // float4 group along x
    const int xq   = xg * 4;
    const int s    = tid >> 3;            // slice 0..31
    const int w    = tid >> 5;            // warp 0..7
    const int lane = tid & 31;

    const size_t base = (size_t)b * T_ * X_ + (size_t)(c * TC_ + s * PT_) * X_ + xq;
    const float4* pp = (const float4*)(phi + base);
    const float4* qq = (const float4*)(psi + base);

    // ---------- phase 1: streaming slice aggregate (lines land in L2) ----------
    float4 A  = make_float4( CUDART_INF_F,  CUDART_INF_F,  CUDART_INF_F,  CUDART_INF_F);
    float4 Bc = make_float4(-CUDART_INF_F, -CUDART_INF_F, -CUDART_INF_F, -CUDART_INF_F);
#pragma unroll
    for (int i = 0; i < PT_; i++) {
        float4 p = pp[i * (X_ / 4)];
        float4 q = qq[i * (X_ / 4)];
        A.x = fminf(p.x, fmaxf(q.x, A.x));  Bc.x = fmaxf(q.x, Bc.x);
        A.y = fminf(p.y, fmaxf(q.y, A.y));  Bc.y = fmaxf(q.y, Bc.y);
        A.z = fminf(p.z, fmaxf(q.z, A.z));  Bc.z = fmaxf(q.z, Bc.z);
        A.w = fminf(p.w, fmaxf(q.w, A.w));  Bc.w = fmaxf(q.w, Bc.w);
    }
    sA[s][xq + 0] = A.x;  sA[s][xq + 1] = A.y;  sA[s][xq + 2] = A.z;  sA[s][xq + 3] = A.w;
    sB[s][xq + 0] = Bc.x; sB[s][xq + 1] = Bc.y; sB[s][xq + 2] = Bc.z; sB[s][xq + 3] = Bc.w;
    __syncwarp();   // slices 4w..4w+3 are written by warp w's own threads

    // ---------- fold level 1: warp w folds its 4 slices (lane = x) ----------
    {
        float wA =  CUDART_INF_F;
        float wB = -CUDART_INF_F;
#pragma unroll
        for (int j = 0; j < SPW_; j++) {
            const int sl = w * SPW_ + j;
            wA = fminf(sA[sl][lane], fmaxf(sB[sl][lane], wA));
            wB = fmaxf(sB[sl][lane], wB);
        }
        sWA[w][lane] = wA;
        sWB[w][lane] = wB;
    }
    __syncthreads();

    // ---------- warp 0: fold level 2 + publish AGG ----------
    if (tid < 32) {
        const int x = tid;
        float Ab =  CUDART_INF_F;
        float Bb = -CUDART_INF_F;
#pragma unroll
        for (int j = 0; j < NW_; j++) {
            Ab = fminf(sWA[j][x], fmaxf(sWB[j][x], Ab));
            Bb = fmaxf(sWB[j][x], Bb);
        }
        sFA[x] = Ab;
        sFB[x] = Bb;
        // chunk 0 never publishes AGG -> lookback can't cross batch boundary
        if (c > 0) {
            g_A[bc * X_ + x]  = Ab;
            g_Bv[bc * X_ + x] = Bb;
            __threadfence();
            __syncwarp();
            if (x == 0) *(volatile int*)&g_flag[bc] = FLAG_AGG;
        }
    }
    __syncthreads();

    // ---------- parallel-window lookback: 8 warps x 1 predecessor per round ----------
    float vin = -LARGE_;                  // meaningful in warp 0 lanes
    if (c > 0) {
        const int batch_lo = b * C_;      // chunk 0 of this batch (always reaches PRE)
        int hi = bc - 1;
        float accA =  CUDART_INF_F;       // warp-0 accumulators across rounds
        float accB = -CUDART_INF_F;
        while (true) {
            const int j = hi - w;         // warp w probes predecessor j
            if (j >= batch_lo) {
                int f;
                do { f = *(volatile int*)&g_flag[j]; } while (f < FLAG_AGG);
                __threadfence();
                const int isPre = (f >= FLAG_PRE);
                wLA[w][lane] = isPre ? g_P[j * X_ + lane] : g_A[j * X_ + lane];
                wLB[w][lane] = isPre ? -CUDART_INF_F      : g_Bv[j * X_ + lane];
                if (lane == 0) wStat[w] = isPre;
            }
            __syncthreads();
            if (tid < 32) {
                const int x = tid;
                int found = 0;
#pragma unroll
                for (int k = 0; k < NW_; k++) {
                    if (hi - k < batch_lo) break;      // unreachable before PRE, safety
                    if (wStat[k]) {                    // PRE: resolve and stop
                        vin = fminf(accA, fmaxf(accB, wLA[k][x]));
                        found = 1;
                        break;
                    }
                    accA = fminf(accA, fmaxf(accB, wLA[k][x]));
                    accB = fmaxf(accB, wLB[k][x]);
                }
                if (x == 0) s_done = found;
            }
            __syncthreads();
            if (s_done) break;
            hi -= NW_;
        }
    }

    // ---------- warp 0: publish PRE first, then fill warp-group carries ----------
    if (tid < 32) {
        const int x = tid;
        float pre = fminf(sFA[x], fmaxf(sFB[x], vin));
        g_P[bc * X_ + x] = pre;
        __threadfence();
        __syncwarp();
        if (x == 0) *(volatile int*)&g_flag[bc] = FLAG_PRE;

        float g = vin;
#pragma unroll
        for (int j = 0; j < NW_; j++) {
            sGC[j][x] = g;
            g = fminf(sWA[j][x], fmaxf(sWB[j][x], g));
        }
    }
    __syncthreads();

    // ---------- per-thread slice carry (walk <=3 slices from warp-group carry) ----------
    float v0 = sGC[w][xq + 0];
    float v1 = sGC[w][xq + 1];
    float v2 = sGC[w][xq + 2];
    float v3 = sGC[w][xq + 3];
    for (int j = w * SPW_; j < s; j++) {
        v0 = fminf(sA[j][xq + 0], fmaxf(sB[j][xq + 0], v0));
        v1 = fminf(sA[j][xq + 1], fmaxf(sB[j][xq + 1], v1));
        v2 = fminf(sA[j][xq + 2], fmaxf(sB[j][xq + 2], v2));
        v3 = fminf(sA[j][xq + 3], fmaxf(sB[j][xq + 3], v3));
    }
    float4 vc = make_float4(v0, v1, v2, v3);

    // ---------- phase 2: reload (L2 hits), apply carry, stream out ----------
    float4* oo = (float4*)(out + base);
#pragma unroll
    for (int i = 0; i < PT_; i++) {
        float4 p = __ldcs(&pp[i * (X_ / 4)]);
        float4 q = __ldcs(&qq[i * (X_ / 4)]);
        vc.x = fminf(p.x, fmaxf(q.x, vc.x));
        vc.y = fminf(p.y, fmaxf(q.y, vc.y));
        vc.z = fminf(p.z, fmaxf(q.z, vc.z));
        vc.w = fminf(p.w, fmaxf(q.w, vc.w));
        __stcs(&oo[i * (X_ / 4)], vc);
    }
}

extern "C" void kernel_launch(void* const* d_in, const int* in_sizes, int n_in,
                              void* d_out, int out_size) {
    const float* phi = (const float*)d_in[0];
    const float* psi = (const float*)d_in[1];
    float* out = (float*)d_out;

    until_scan<<<NB_, 256>>>(phi, psi, out);
}